// round 1
// baseline (speedup 1.0000x reference)
#include <cuda_runtime.h>
#include <cuda_bf16.h>
#include <math.h>

#define N_NODES_MAX 200000
#define N_QUERY_MAX 131072
#define FEAT 9
#define HID 64
#define OUT 128

// ---------------- static device scratch (no runtime allocation) ----------------
__device__ float4 g_geom4[N_NODES_MAX];           // padded geometry (3.2 MB)
__device__ float  g_mom [N_QUERY_MAX * 12];       // raw moments per query (6.3 MB)
__device__ float  g_feat[N_QUERY_MAX * FEAT];     // features (4.7 MB)
__device__ double g_sums[2 * FEAT];               // column sum / sumsq
__device__ float  g_norm[2 * FEAT];               // mean / inv-std factor

// ---------------- K1: pad geometry to float4 ----------------
__global__ void pad_geom_kernel(const float* __restrict__ geom, int n) {
    int i = blockIdx.x * blockDim.x + threadIdx.x;
    if (i < n) {
        float4 p;
        p.x = geom[3 * i + 0];
        p.y = geom[3 * i + 1];
        p.z = geom[3 * i + 2];
        p.w = 0.f;
        g_geom4[i] = p;
    }
}

// ---------------- warp sum helper ----------------
__device__ __forceinline__ float wsum(float v) {
#pragma unroll
    for (int o = 16; o; o >>= 1) v += __shfl_xor_sync(0xffffffffu, v, o);
    return v;
}

// ---------------- K2: per-query moments (one warp per query) ----------------
__global__ void moments_kernel(const float* __restrict__ lq,
                               const int* __restrict__ nidx,
                               const int* __restrict__ rs,
                               int Qn) {
    int warp = (blockIdx.x * blockDim.x + threadIdx.x) >> 5;
    int lane = threadIdx.x & 31;
    if (warp >= Qn) return;

    int start = rs[warp];
    int end   = rs[warp + 1];
    float qx = __ldg(&lq[3 * warp + 0]);
    float qy = __ldg(&lq[3 * warp + 1]);
    float qz = __ldg(&lq[3 * warp + 2]);

    float sd = 0.f, sd2 = 0.f;
    float sx = 0.f, sy = 0.f, sz = 0.f;
    float sxx = 0.f, sxy = 0.f, sxz = 0.f, syy = 0.f, syz = 0.f, szz = 0.f;

    for (int e = start + lane; e < end; e += 32) {
        int id = __ldg(&nidx[e]);
        float4 p = g_geom4[id];
        float dx = p.x - qx, dy = p.y - qy, dz = p.z - qz;
        float d2 = dx * dx + dy * dy + dz * dz;
        sd  += sqrtf(d2);
        sd2 += d2;
        sx += p.x; sy += p.y; sz += p.z;
        sxx += p.x * p.x; sxy += p.x * p.y; sxz += p.x * p.z;
        syy += p.y * p.y; syz += p.y * p.z; szz += p.z * p.z;
    }

    sd = wsum(sd);   sd2 = wsum(sd2);
    sx = wsum(sx);   sy  = wsum(sy);   sz  = wsum(sz);
    sxx = wsum(sxx); sxy = wsum(sxy); sxz = wsum(sxz);
    syy = wsum(syy); syz = wsum(syz); szz = wsum(szz);

    if (lane == 0) {
        float* m = &g_mom[warp * 12];
        m[0] = (float)(end - start);
        m[1] = sd;  m[2] = sd2;
        m[3] = sx;  m[4] = sy;  m[5] = sz;
        m[6] = sxx; m[7] = sxy; m[8] = sxz;
        m[9] = syy; m[10] = syz; m[11] = szz;
    }
}

// ---------------- K3: feature finalize + 3x3 symmetric eigensolve ----------------
__global__ void features_kernel(const float* __restrict__ lq, int Qn) {
    int q = blockIdx.x * blockDim.x + threadIdx.x;
    if (q >= Qn) return;

    const float* m = &g_mom[q * 12];
    float cnt = m[0];
    float* f = &g_feat[q * FEAT];

    if (cnt < 0.5f) {
#pragma unroll
        for (int i = 0; i < FEAT; i++) f[i] = 0.f;
        return;
    }

    float denom = fmaxf(cnt, 1.f);
    float inv = 1.f / denom;

    float davg = m[1] * inv;
    float ex2  = m[2] * inv;
    float dvar = fmaxf(ex2 - davg * davg, 0.f);

    float cx = m[3] * inv, cy = m[4] * inv, cz = m[5] * inv;
    float qx = __ldg(&lq[3 * q + 0]);
    float qy = __ldg(&lq[3 * q + 1]);
    float qz = __ldg(&lq[3 * q + 2]);
    float Dx = cx - qx, Dy = cy - qy, Dz = cz - qz;

    // covariance = E[xx^T] - c c^T
    float a = m[6] * inv - cx * cx;
    float b = m[9] * inv - cy * cy;
    float c = m[11] * inv - cz * cz;
    float d = m[7] * inv - cx * cy;
    float e = m[8] * inv - cx * cz;
    float ff = m[10] * inv - cy * cz;

    // analytic symmetric 3x3 eigenvalues (descending)
    float e1, e2, e3;
    float p1 = d * d + e * e + ff * ff;
    float qm = (a + b + c) * (1.f / 3.f);
    float aa = a - qm, bb = b - qm, cc = c - qm;
    float p2 = aa * aa + bb * bb + cc * cc + 2.f * p1;
    if (p2 <= 1e-22f) {
        e1 = e2 = e3 = qm;
    } else {
        float p = sqrtf(p2 * (1.f / 6.f));
        float ip = 1.f / p;
        float b11 = aa * ip, b22 = bb * ip, b33 = cc * ip;
        float b12 = d * ip, b13 = e * ip, b23 = ff * ip;
        float r = 0.5f * (b11 * (b22 * b33 - b23 * b23)
                        - b12 * (b12 * b33 - b23 * b13)
                        + b13 * (b12 * b23 - b22 * b13));
        r = fminf(fmaxf(r, -1.f), 1.f);
        float phi = acosf(r) * (1.f / 3.f);
        e1 = qm + 2.f * p * cosf(phi);
        e3 = qm + 2.f * p * cosf(phi + 2.0943951023931953f);
        e2 = 3.f * qm - e1 - e3;
    }

    f[0] = cnt; f[1] = davg; f[2] = dvar;
    f[3] = Dx;  f[4] = Dy;   f[5] = Dz;
    f[6] = e1;  f[7] = e2;   f[8] = e3;
}

// ---------------- K4a: zero the accumulators ----------------
__global__ void zero_sums_kernel() {
    int t = threadIdx.x;
    if (t < 2 * FEAT) g_sums[t] = 0.0;
}

// ---------------- K4b: column reduction (sum, sumsq) in double ----------------
__global__ void colreduce_kernel(int Qn) {
    double s[FEAT], s2[FEAT];
#pragma unroll
    for (int c = 0; c < FEAT; c++) { s[c] = 0.0; s2[c] = 0.0; }

    int stride = gridDim.x * blockDim.x;
    for (int r = blockIdx.x * blockDim.x + threadIdx.x; r < Qn; r += stride) {
#pragma unroll
        for (int c = 0; c < FEAT; c++) {
            double v = (double)g_feat[r * FEAT + c];
            s[c] += v;
            s2[c] += v * v;
        }
    }
    // warp reduce doubles
#pragma unroll
    for (int c = 0; c < FEAT; c++) {
#pragma unroll
        for (int o = 16; o; o >>= 1) {
            s[c]  += __shfl_xor_sync(0xffffffffu, s[c], o);
            s2[c] += __shfl_xor_sync(0xffffffffu, s2[c], o);
        }
    }
    if ((threadIdx.x & 31) == 0) {
#pragma unroll
        for (int c = 0; c < FEAT; c++) {
            atomicAdd(&g_sums[c], s[c]);
            atomicAdd(&g_sums[FEAT + c], s2[c]);
        }
    }
}

// ---------------- K5: finalize normalization params ----------------
__global__ void finalize_norm_kernel(int Qn) {
    int c = threadIdx.x;
    if (c < FEAT) {
        double Qd = (double)Qn;
        double mean = g_sums[c] / Qd;
        double var = (g_sums[FEAT + c] - Qd * mean * mean) / (Qd - 1.0);
        if (var < 0.0) var = 0.0;
        double sd = sqrt(var);
        g_norm[c] = (float)mean;
        g_norm[FEAT + c] = (sd < 1e-6) ? 1.0f : (float)(1.0 / sd);
    }
}

// ---------------- K6: fused MLP ----------------
// shared layout (floats):
#define OFF_W2   0          // 64*128 = 8192
#define OFF_W1   8192       // 9*64   = 576
#define OFF_B1   8768       // 64
#define OFF_B2   8832       // 128
#define OFF_MEAN 8960       // 9
#define OFF_FAC  8969       // 9
#define OFF_H    8992       // 64*256 = 16384
#define MLP_SMEM_FLOATS (OFF_H + HID * 256)
#define MLP_SMEM_BYTES  (MLP_SMEM_FLOATS * 4)

__global__ __launch_bounds__(256, 2)
void mlp_kernel(const float* __restrict__ gW1, const float* __restrict__ gb1,
                const float* __restrict__ gW2, const float* __restrict__ gb2,
                float* __restrict__ out, int Qn) {
    extern __shared__ float smem[];
    int tid = threadIdx.x;

    for (int i = tid; i < HID * OUT; i += 256) smem[OFF_W2 + i] = gW2[i];
    for (int i = tid; i < FEAT * HID; i += 256) smem[OFF_W1 + i] = gW1[i];
    for (int i = tid; i < HID; i += 256)  smem[OFF_B1 + i] = gb1[i];
    for (int i = tid; i < OUT; i += 256)  smem[OFF_B2 + i] = gb2[i];
    for (int i = tid; i < 2 * FEAT; i += 256) smem[OFF_MEAN + i] = g_norm[i];
    __syncthreads();

    int q = blockIdx.x * 256 + tid;
    if (q >= Qn) return;

    // normalized features in registers
    float fn[FEAT];
#pragma unroll
    for (int i = 0; i < FEAT; i++)
        fn[i] = (g_feat[q * FEAT + i] - smem[OFF_MEAN + i]) * smem[OFF_FAC + i];

    // layer 1 -> h in shared (conflict-free column per thread)
    float* hs = &smem[OFF_H];
#pragma unroll 4
    for (int o = 0; o < HID; o++) {
        float acc = smem[OFF_B1 + o];
#pragma unroll
        for (int ff = 0; ff < FEAT; ff++)
            acc += fn[ff] * smem[OFF_W1 + ff * HID + o];
        hs[o * 256 + tid] = fmaxf(acc, 0.f);
    }

    // layer 2, 32 outputs per pass
    float* outq = &out[(long long)q * OUT];
#pragma unroll
    for (int ob = 0; ob < OUT; ob += 32) {
        float acc[32];
#pragma unroll
        for (int j = 0; j < 32; j++) acc[j] = smem[OFF_B2 + ob + j];
#pragma unroll 4
        for (int k = 0; k < HID; k++) {
            float hk = hs[k * 256 + tid];
            const float* w2row = &smem[OFF_W2 + k * OUT + ob];
#pragma unroll
            for (int j = 0; j < 32; j++) acc[j] += hk * w2row[j];
        }
#pragma unroll
        for (int j = 0; j < 32; j++) outq[ob + j] = fmaxf(acc[j], 0.f);
    }
}

// ---------------- launch ----------------
extern "C" void kernel_launch(void* const* d_in, const int* in_sizes, int n_in,
                              void* d_out, int out_size) {
    const float* geom = (const float*)d_in[0];
    const float* lq   = (const float*)d_in[1];
    const int*   nidx = (const int*)d_in[2];
    const int*   rs   = (const int*)d_in[3];
    const float* W1   = (const float*)d_in[4];
    const float* b1   = (const float*)d_in[5];
    const float* W2   = (const float*)d_in[6];
    const float* b2   = (const float*)d_in[7];
    float* out = (float*)d_out;

    int nnodes = in_sizes[0] / 3;
    int Qn = in_sizes[3] - 1;

    pad_geom_kernel<<<(nnodes + 255) / 256, 256>>>(geom, nnodes);
    moments_kernel<<<(Qn + 7) / 8, 256>>>(lq, nidx, rs, Qn);
    features_kernel<<<(Qn + 255) / 256, 256>>>(lq, Qn);
    zero_sums_kernel<<<1, 32>>>();
    colreduce_kernel<<<256, 256>>>(Qn);
    finalize_norm_kernel<<<1, 32>>>(Qn);

    cudaFuncSetAttribute(mlp_kernel, cudaFuncAttributeMaxDynamicSharedMemorySize,
                         MLP_SMEM_BYTES);
    mlp_kernel<<<(Qn + 255) / 256, 256, MLP_SMEM_BYTES>>>(W1, b1, W2, b2, out, Qn);
}

// round 2
// speedup vs baseline: 1.9025x; 1.9025x over previous
#include <cuda_runtime.h>
#include <cuda_bf16.h>
#include <math.h>

#define N_NODES_MAX 200000
#define N_QUERY_MAX 131072
#define FEAT 9
#define HID 64
#define OUT 128

typedef unsigned long long ull;

// ---------------- static device scratch ----------------
__device__ float4 g_geom4[N_NODES_MAX];
__device__ float  g_feat[N_QUERY_MAX * FEAT];
__device__ double g_sums[2 * FEAT];
__device__ float  g_norm[2 * FEAT];

// ---------------- f32x2 helpers (Blackwell packed fp32) ----------------
__device__ __forceinline__ ull pk2(float lo, float hi) {
    ull r; asm("mov.b64 %0,{%1,%2};" : "=l"(r) : "f"(lo), "f"(hi)); return r;
}
__device__ __forceinline__ void upk2(float& lo, float& hi, ull v) {
    asm("mov.b64 {%0,%1},%2;" : "=f"(lo), "=f"(hi) : "l"(v));
}
__device__ __forceinline__ ull fma2(ull a, ull b, ull c) {
    ull d; asm("fma.rn.f32x2 %0,%1,%2,%3;" : "=l"(d) : "l"(a), "l"(b), "l"(c));
    return d;
}

// ---------------- K1: pad geometry to float4 ----------------
__global__ void pad_geom_kernel(const float* __restrict__ geom, int n) {
    int i = blockIdx.x * blockDim.x + threadIdx.x;
    if (i < n) {
        float4 p;
        p.x = geom[3 * i + 0];
        p.y = geom[3 * i + 1];
        p.z = geom[3 * i + 2];
        p.w = 0.f;
        g_geom4[i] = p;
    }
}

// ---------------- K2: zero accumulators ----------------
__global__ void zero_sums_kernel() {
    int t = threadIdx.x;
    if (t < 2 * FEAT) g_sums[t] = 0.0;
}

// ---------------- K3: fused moments + features + column reduction ----------------
// Thread per query: sequential neighbor accumulation (no shuffles in hot path),
// in-thread 3x3 eigensolve, then block-level double reduction -> atomics.
__global__ __launch_bounds__(256)
void moments_feat_kernel(const float* __restrict__ lq,
                         const int* __restrict__ nidx,
                         const int* __restrict__ rs,
                         int Qn) {
    int q = blockIdx.x * blockDim.x + threadIdx.x;
    bool valid = (q < Qn);
    int qc = valid ? q : (Qn - 1);

    float f[FEAT];
#pragma unroll
    for (int i = 0; i < FEAT; i++) f[i] = 0.f;

    {
        int start = rs[qc];
        int end   = rs[qc + 1];
        int cnt   = end - start;

        float qx = __ldg(&lq[3 * qc + 0]);
        float qy = __ldg(&lq[3 * qc + 1]);
        float qz = __ldg(&lq[3 * qc + 2]);

        float sd = 0.f, sd2 = 0.f;
        float sx = 0.f, sy = 0.f, sz = 0.f;
        float sxx = 0.f, sxy = 0.f, sxz = 0.f, syy = 0.f, syz = 0.f, szz = 0.f;

        if (cnt == 32 && (start & 3) == 0) {
            // fast path: vectorized index loads, 32 gathers in flight
            const int4* ip = (const int4*)(nidx + start);
            int4 iv[8];
#pragma unroll
            for (int i = 0; i < 8; i++) iv[i] = __ldg(&ip[i]);
            const int* idf = (const int*)iv;
#pragma unroll
            for (int e = 0; e < 32; e++) {
                float4 p = g_geom4[idf[e]];
                float dx = p.x - qx, dy = p.y - qy, dz = p.z - qz;
                float d2 = dx * dx + dy * dy + dz * dz;
                sd  += sqrtf(d2);
                sd2 += d2;
                sx += p.x; sy += p.y; sz += p.z;
                sxx += p.x * p.x; sxy += p.x * p.y; sxz += p.x * p.z;
                syy += p.y * p.y; syz += p.y * p.z; szz += p.z * p.z;
            }
        } else {
            for (int e = start; e < end; e++) {
                int id = __ldg(&nidx[e]);
                float4 p = g_geom4[id];
                float dx = p.x - qx, dy = p.y - qy, dz = p.z - qz;
                float d2 = dx * dx + dy * dy + dz * dz;
                sd  += sqrtf(d2);
                sd2 += d2;
                sx += p.x; sy += p.y; sz += p.z;
                sxx += p.x * p.x; sxy += p.x * p.y; sxz += p.x * p.z;
                syy += p.y * p.y; syz += p.y * p.z; szz += p.z * p.z;
            }
        }

        if (valid && cnt > 0) {
            float fcnt = (float)cnt;
            float inv = 1.f / fmaxf(fcnt, 1.f);

            float davg = sd * inv;
            float ex2  = sd2 * inv;
            float dvar = fmaxf(ex2 - davg * davg, 0.f);

            float cx = sx * inv, cy = sy * inv, cz = sz * inv;

            float a = sxx * inv - cx * cx;
            float b = syy * inv - cy * cy;
            float c = szz * inv - cz * cz;
            float d = sxy * inv - cx * cy;
            float e = sxz * inv - cx * cz;
            float ff = syz * inv - cy * cz;

            float e1, e2, e3;
            float p1 = d * d + e * e + ff * ff;
            float qm = (a + b + c) * (1.f / 3.f);
            float aa = a - qm, bb = b - qm, cc = c - qm;
            float p2 = aa * aa + bb * bb + cc * cc + 2.f * p1;
            if (p2 <= 1e-22f) {
                e1 = e2 = e3 = qm;
            } else {
                float p = sqrtf(p2 * (1.f / 6.f));
                float ipv = 1.f / p;
                float b11 = aa * ipv, b22 = bb * ipv, b33 = cc * ipv;
                float b12 = d * ipv, b13 = e * ipv, b23 = ff * ipv;
                float r = 0.5f * (b11 * (b22 * b33 - b23 * b23)
                                - b12 * (b12 * b33 - b23 * b13)
                                + b13 * (b12 * b23 - b22 * b13));
                r = fminf(fmaxf(r, -1.f), 1.f);
                float phi = acosf(r) * (1.f / 3.f);
                e1 = qm + 2.f * p * cosf(phi);
                e3 = qm + 2.f * p * cosf(phi + 2.0943951023931953f);
                e2 = 3.f * qm - e1 - e3;
            }

            f[0] = fcnt; f[1] = davg; f[2] = dvar;
            f[3] = cx - qx; f[4] = cy - qy; f[5] = cz - qz;
            f[6] = e1; f[7] = e2; f[8] = e3;
        }
    }

    if (valid) {
        float* fo = &g_feat[q * FEAT];
#pragma unroll
        for (int i = 0; i < FEAT; i++) fo[i] = f[i];
    }

    // block reduction of column sums/sumsqs in double
    double s[FEAT], s2[FEAT];
#pragma unroll
    for (int i = 0; i < FEAT; i++) {
        double v = valid ? (double)f[i] : 0.0;
        s[i] = v; s2[i] = v * v;
    }
#pragma unroll
    for (int i = 0; i < FEAT; i++) {
#pragma unroll
        for (int o = 16; o; o >>= 1) {
            s[i]  += __shfl_xor_sync(0xffffffffu, s[i], o);
            s2[i] += __shfl_xor_sync(0xffffffffu, s2[i], o);
        }
    }

    __shared__ double red[8][2 * FEAT];
    int warp = threadIdx.x >> 5, lane = threadIdx.x & 31;
    if (lane == 0) {
#pragma unroll
        for (int i = 0; i < FEAT; i++) {
            red[warp][i] = s[i];
            red[warp][FEAT + i] = s2[i];
        }
    }
    __syncthreads();
    if (threadIdx.x < 2 * FEAT) {
        double t = 0.0;
#pragma unroll
        for (int w = 0; w < 8; w++) t += red[w][threadIdx.x];
        atomicAdd(&g_sums[threadIdx.x], t);
    }
}

// ---------------- K4: finalize normalization ----------------
__global__ void finalize_norm_kernel(int Qn) {
    int c = threadIdx.x;
    if (c < FEAT) {
        double Qd = (double)Qn;
        double mean = g_sums[c] / Qd;
        double var = (g_sums[FEAT + c] - Qd * mean * mean) / (Qd - 1.0);
        if (var < 0.0) var = 0.0;
        double sd = sqrt(var);
        g_norm[c] = (float)mean;
        g_norm[FEAT + c] = (sd < 1e-6) ? 1.0f : (float)(1.0 / sd);
    }
}

// ---------------- K5: fused MLP with packed f32x2 FFMA ----------------
// smem layout (floats)
#define OFF_W2   0                     // 64*128 = 8192
#define OFF_W1   (OFF_W2 + HID * OUT)  // 576
#define OFF_B1   (OFF_W1 + FEAT * HID) // 64
#define OFF_B2   (OFF_B1 + HID)        // 128
#define OFF_NRM  (OFF_B2 + OUT)        // 18
#define OFF_STG  (OFF_NRM + 32)        // stage: 32 * 129
#define STG_STRIDE 129
#define MLP_SMEM_FLOATS (OFF_STG + 32 * STG_STRIDE)
#define MLP_SMEM_BYTES  (MLP_SMEM_FLOATS * 4)
#define QB 128

__global__ __launch_bounds__(QB, 3)
void mlp_kernel(const float* __restrict__ gW1, const float* __restrict__ gb1,
                const float* __restrict__ gW2, const float* __restrict__ gb2,
                float* __restrict__ out, int Qn) {
    extern __shared__ float sm[];
    int tid = threadIdx.x;

    // cooperative weight load (vectorized)
    {
        const float4* w2v = (const float4*)gW2;
        float4* d = (float4*)&sm[OFF_W2];
#pragma unroll
        for (int i = 0; i < (HID * OUT / 4) / QB; i++)
            d[tid + i * QB] = w2v[tid + i * QB];
        for (int i = tid; i < FEAT * HID; i += QB) sm[OFF_W1 + i] = gW1[i];
        if (tid < HID) sm[OFF_B1 + tid] = gb1[tid];
        if (tid < OUT) sm[OFF_B2 + tid] = gb2[tid];
        if (tid < 2 * FEAT) sm[OFF_NRM + tid] = g_norm[tid];
    }
    __syncthreads();

    int qb = blockIdx.x * QB;
    int q = qb + tid;
    int qc = (q < Qn) ? q : (Qn - 1);

    // normalized features (splat-packed)
    ull fnp[FEAT];
    {
        const float* frow = &g_feat[(size_t)qc * FEAT];
#pragma unroll
        for (int i = 0; i < FEAT; i++) {
            float v = (frow[i] - sm[OFF_NRM + i]) * sm[OFF_NRM + FEAT + i];
            fnp[i] = pk2(v, v);
        }
    }

    // layer 1: h[64] in registers, packed over output pairs
    float h[HID];
#pragma unroll
    for (int op = 0; op < HID / 2; op++) {
        ull acc = *(const ull*)&sm[OFF_B1 + 2 * op];
#pragma unroll
        for (int ff = 0; ff < FEAT; ff++)
            acc = fma2(fnp[ff], *(const ull*)&sm[OFF_W1 + ff * HID + 2 * op], acc);
        float lo, hi; upk2(lo, hi, acc);
        h[2 * op]     = fmaxf(lo, 0.f);
        h[2 * op + 1] = fmaxf(hi, 0.f);
    }

    int lane = tid & 31, w = tid >> 5;

    // layer 2: 4 passes of 32 outputs (16 f32x2 accumulators)
#pragma unroll 1
    for (int pass = 0; pass < 4; pass++) {
        ull acc[16];
#pragma unroll
        for (int j = 0; j < 16; j++)
            acc[j] = *(const ull*)&sm[OFF_B2 + pass * 32 + 2 * j];

#pragma unroll
        for (int k = 0; k < HID; k++) {
            ull hk = pk2(h[k], h[k]);
            const float* wr = &sm[OFF_W2 + k * OUT + pass * 32];
#pragma unroll
            for (int jj = 0; jj < 8; jj++) {
                ulonglong2 wv = *(const ulonglong2*)(wr + 4 * jj);
                acc[2 * jj]     = fma2(hk, wv.x, acc[2 * jj]);
                acc[2 * jj + 1] = fma2(hk, wv.y, acc[2 * jj + 1]);
            }
        }

        // relu + stage (j-major, conflict-free)
#pragma unroll
        for (int j = 0; j < 16; j++) {
            float lo, hi; upk2(lo, hi, acc[j]);
            sm[OFF_STG + (2 * j) * STG_STRIDE + tid]     = fmaxf(lo, 0.f);
            sm[OFF_STG + (2 * j + 1) * STG_STRIDE + tid] = fmaxf(hi, 0.f);
        }
        __syncthreads();

        // coalesced store: warp w handles query (it*4 + w), lane = output j
#pragma unroll 4
        for (int it = 0; it < 32; it++) {
            int ql = it * 4 + w;
            int gq = qb + ql;
            if (gq < Qn)
                out[(size_t)gq * OUT + pass * 32 + lane] =
                    sm[OFF_STG + lane * STG_STRIDE + ql];
        }
        __syncthreads();
    }
}

// ---------------- launch ----------------
extern "C" void kernel_launch(void* const* d_in, const int* in_sizes, int n_in,
                              void* d_out, int out_size) {
    const float* geom = (const float*)d_in[0];
    const float* lq   = (const float*)d_in[1];
    const int*   nidx = (const int*)d_in[2];
    const int*   rs   = (const int*)d_in[3];
    const float* W1   = (const float*)d_in[4];
    const float* b1   = (const float*)d_in[5];
    const float* W2   = (const float*)d_in[6];
    const float* b2   = (const float*)d_in[7];
    float* out = (float*)d_out;

    int nnodes = in_sizes[0] / 3;
    int Qn = in_sizes[3] - 1;

    pad_geom_kernel<<<(nnodes + 255) / 256, 256>>>(geom, nnodes);
    zero_sums_kernel<<<1, 32>>>();
    moments_feat_kernel<<<(Qn + 255) / 256, 256>>>(lq, nidx, rs, Qn);
    finalize_norm_kernel<<<1, 32>>>(Qn);

    cudaFuncSetAttribute(mlp_kernel, cudaFuncAttributeMaxDynamicSharedMemorySize,
                         MLP_SMEM_BYTES);
    mlp_kernel<<<(Qn + QB - 1) / QB, QB, MLP_SMEM_BYTES>>>(W1, b1, W2, b2, out, Qn);
}